// round 3
// baseline (speedup 1.0000x reference)
#include <cuda_runtime.h>

// Problem dims (fixed by the reference)
#define Bn  4
#define Qn  256
#define KVn 1024
#define Hn  128
#define VSn 256

// Scratch for projected q and k (no cudaMalloc allowed)
__device__ float g_qp[Bn * Qn * Hn];    // [B*Q, H]
__device__ float g_kp[Bn * KVn * Hn];   // [B*KV, H]

// ---------------------------------------------------------------------------
// Kernel 1: project queries->g_qp and keys->g_kp.
// Each block handles 8 rows. 128 threads: thread t owns output column t.
// W column access is coalesced; input rows staged in smem and broadcast.
// ---------------------------------------------------------------------------
__global__ void proj_kernel(const float* __restrict__ queries,
                            const float* __restrict__ keys,
                            const float* __restrict__ Wq,
                            const float* __restrict__ Wk) {
    const int r0 = blockIdx.x * 8;
    const float* in;
    const float* W;
    float* outp;
    if (r0 < Bn * Qn) {
        in   = queries + r0 * Hn;
        W    = Wq;
        outp = g_qp + r0 * Hn;
    } else {
        const int rr = r0 - Bn * Qn;
        in   = keys + rr * Hn;
        W    = Wk;
        outp = g_kp + rr * Hn;
    }
    __shared__ float s[8][Hn];
    const int t = threadIdx.x;
    #pragma unroll
    for (int rr = 0; rr < 8; rr++) s[rr][t] = in[rr * Hn + t];
    __syncthreads();

    float a[8];
    #pragma unroll
    for (int rr = 0; rr < 8; rr++) a[rr] = 0.f;

    #pragma unroll 4
    for (int kk = 0; kk < Hn; kk++) {
        const float w = W[kk * Hn + t];
        #pragma unroll
        for (int rr = 0; rr < 8; rr++)
            a[rr] = fmaf(s[rr][kk], w, a[rr]);
    }
    #pragma unroll
    for (int rr = 0; rr < 8; rr++) outp[rr * Hn + t] = a[rr];
}

// ---------------------------------------------------------------------------
// Accurate fast tanh: tanh(x) = sign(x) * (1 - 2/(1 + e^{2|x|}))
// ex2.approx + rcp.approx are each ~2^-22 rel err -> abs error < ~4e-7.
// Overflow-safe: large |x| -> ex2 = inf -> rcp = 0 -> tanh = sign(x)*1.
// ---------------------------------------------------------------------------
__device__ __forceinline__ float tanh_acc(float x) {
    const float ax = fabsf(x);
    float e;
    asm("ex2.approx.f32 %0, %1;" : "=f"(e) : "f"(ax * 2.885390081777927f)); // 2*log2(e)
    float r;
    asm("rcp.approx.f32 %0, %1;" : "=f"(r) : "f"(e + 1.0f));
    const float t = fmaf(-2.0f, r, 1.0f);
    return copysignf(t, x);
}

// Per-lane partial score for one key (lane owns 4 h-elements).
__device__ __forceinline__ float score4(const float4 q4, const float4 w4,
                                        const float4 k4) {
    float s = w4.x * tanh_acc(q4.x + k4.x);
    s = fmaf(w4.y, tanh_acc(q4.y + k4.y), s);
    s = fmaf(w4.z, tanh_acc(q4.z + k4.z), s);
    s = fmaf(w4.w, tanh_acc(q4.w + k4.w), s);
    return s;
}

// ---------------------------------------------------------------------------
// Kernel 2: one block per (b, i) query row. 256 threads (8 warps).
// Pass 1: warp-per-key scores, 2 keys/iter, loads pipelined 2 deep.
// Pass 2: block softmax, exactly matching the -1e6 masking semantics;
//         valid_len == 0 degenerates to uniform weights over all KV.
// Pass 3: thread-per-output-column weighted sum of values, ILP 8.
// ---------------------------------------------------------------------------
__global__ void attn_kernel(const float* __restrict__ values,
                            const int* __restrict__ valid_lens,
                            const float* __restrict__ wv,
                            float* __restrict__ out) {
    const int blk  = blockIdx.x;
    const int b    = blk & 3;                    // batch-interleaved mapping
    const int row  = (b << 8) | (blk >> 2);      // b*256 + i
    const int tid  = threadIdx.x;
    const int lane = tid & 31;
    const int warp = tid >> 5;

    __shared__ float s_sc[KVn];
    __shared__ float s_rmax[8];
    __shared__ float s_rsum[8];

    const int L     = valid_lens[b];
    const bool uni  = (L <= 0);        // all slots masked -> uniform softmax
    const int effL  = uni ? KVn : L;

    float Z;
    if (!uni) {
        // ---- Pass 1: scores, software-pipelined, 2 keys per iteration ----
        const float4 q4 = *reinterpret_cast<const float4*>(&g_qp[row * Hn + lane * 4]);
        const float4 w4 = *reinterpret_cast<const float4*>(&wv[lane * 4]);
        const float* kbase = g_kp + b * KVn * Hn;

        int j = warp;
        if (j < effL) {
            // prime pipeline (indices clamped into valid range -> safe loads)
            int jB = (j + 8 < effL) ? j + 8 : j;
            float4 ka = *reinterpret_cast<const float4*>(&kbase[j  * Hn + lane * 4]);
            float4 kb = *reinterpret_cast<const float4*>(&kbase[jB * Hn + lane * 4]);

            while (j < effL) {
                const int jn  = j + 16;
                const int jA2 = (jn     < effL) ? jn     : j;
                const int jB2 = (jn + 8 < effL) ? jn + 8 : j;
                const float4 kc = *reinterpret_cast<const float4*>(&kbase[jA2 * Hn + lane * 4]);
                const float4 kd = *reinterpret_cast<const float4*>(&kbase[jB2 * Hn + lane * 4]);

                // two independent MUFU chains
                float s0 = score4(q4, w4, ka);
                float s1 = score4(q4, w4, kb);

                // interleaved butterfly reductions (pipeline the SHFL latency)
                #pragma unroll
                for (int o = 16; o > 0; o >>= 1) {
                    s0 += __shfl_xor_sync(0xffffffffu, s0, o);
                    s1 += __shfl_xor_sync(0xffffffffu, s1, o);
                }
                if (lane == 0) {
                    s_sc[j] = s0;
                    if (j + 8 < effL) s_sc[j + 8] = s1;
                }
                ka = kc;
                kb = kd;
                j  = jn;
            }
        }
        __syncthreads();

        // ---- Pass 2a: block max over [0, effL) ----
        float m = -3.0e38f;
        for (int jj = tid; jj < effL; jj += 256) m = fmaxf(m, s_sc[jj]);
        #pragma unroll
        for (int o = 16; o > 0; o >>= 1)
            m = fmaxf(m, __shfl_xor_sync(0xffffffffu, m, o));
        if (lane == 0) s_rmax[warp] = m;
        __syncthreads();
        float M = s_rmax[0];
        #pragma unroll
        for (int k = 1; k < 8; k++) M = fmaxf(M, s_rmax[k]);

        // ---- Pass 2b: exp + sum ----
        float z = 0.f;
        for (int jj = tid; jj < effL; jj += 256) {
            const float e = __expf(s_sc[jj] - M);
            s_sc[jj] = e;
            z += e;
        }
        #pragma unroll
        for (int o = 16; o > 0; o >>= 1)
            z += __shfl_xor_sync(0xffffffffu, z, o);
        if (lane == 0) s_rsum[warp] = z;
        __syncthreads();
        Z = s_rsum[0];
        #pragma unroll
        for (int k = 1; k < 8; k++) Z += s_rsum[k];
    } else {
        // valid_len == 0: reference gives softmax over all -1e6 -> uniform
        for (int jj = tid; jj < KVn; jj += 256) s_sc[jj] = 1.0f;
        __syncthreads();
        Z = (float)KVn;
    }

    // ---- Pass 3: AV. Thread tid owns output column tid. ILP 8. ----
    const int c = tid;
    const float* vb = values + (size_t)b * KVn * VSn + c;
    float a[8];
    #pragma unroll
    for (int u = 0; u < 8; u++) a[u] = 0.f;

    int j = 0;
    for (; j + 8 <= effL; j += 8) {
        #pragma unroll
        for (int u = 0; u < 8; u++)
            a[u] = fmaf(s_sc[j + u], vb[(j + u) * VSn], a[u]);
    }
    for (; j < effL; j++) a[0] = fmaf(s_sc[j], vb[j * VSn], a[0]);

    const float acc = ((a[0] + a[1]) + (a[2] + a[3])) +
                      ((a[4] + a[5]) + (a[6] + a[7]));
    out[row * VSn + c] = acc / Z;
}

// ---------------------------------------------------------------------------
extern "C" void kernel_launch(void* const* d_in, const int* in_sizes, int n_in,
                              void* d_out, int out_size) {
    const float* queries = (const float*)d_in[0];
    const float* keys    = (const float*)d_in[1];
    const float* values  = (const float*)d_in[2];
    const int*   valid   = (const int*)d_in[3];
    const float* Wq      = (const float*)d_in[4];
    const float* Wk      = (const float*)d_in[5];
    const float* wv      = (const float*)d_in[6];
    float* out           = (float*)d_out;

    proj_kernel<<<(Bn * Qn + Bn * KVn) / 8, 128>>>(queries, keys, Wq, Wk);
    attn_kernel<<<Bn * Qn, 256>>>(values, valid, wv, out);
}

// round 4
// speedup vs baseline: 1.4850x; 1.4850x over previous
#include <cuda_runtime.h>

// Problem dims (fixed by the reference)
#define Bn  4
#define Qn  256
#define KVn 1024
#define Hn  128
#define VSn 256

// Scratch: Eq = e^{2*clamp(q_proj)}, Ek = e^{2*clamp(k_proj)}
__device__ float g_Eq[Bn * Qn * Hn];    // [B*Q, H]
__device__ float g_Ek[Bn * KVn * Hn];   // [B*KV, H]

// 2*log2(e): e^{2x} = 2^{x * 2*log2(e)}
#define TWO_LOG2E 2.885390081777927f

// ---------------------------------------------------------------------------
// Kernel 1: project rows and emit E = exp2(clamp(proj, +-40) * 2*log2(e)).
// Each block handles 8 rows; thread t owns output column t.
// ---------------------------------------------------------------------------
__global__ void proj_kernel(const float* __restrict__ queries,
                            const float* __restrict__ keys,
                            const float* __restrict__ Wq,
                            const float* __restrict__ Wk) {
    const int r0 = blockIdx.x * 8;
    const float* in;
    const float* W;
    float* outp;
    if (r0 < Bn * Qn) {
        in   = queries + r0 * Hn;
        W    = Wq;
        outp = g_Eq + r0 * Hn;
    } else {
        const int rr = r0 - Bn * Qn;
        in   = keys + rr * Hn;
        W    = Wk;
        outp = g_Ek + rr * Hn;
    }
    __shared__ float s[8][Hn];
    const int t = threadIdx.x;
    #pragma unroll
    for (int rr = 0; rr < 8; rr++) s[rr][t] = in[rr * Hn + t];
    __syncthreads();

    float a[8];
    #pragma unroll
    for (int rr = 0; rr < 8; rr++) a[rr] = 0.f;

    #pragma unroll 4
    for (int kk = 0; kk < Hn; kk++) {
        const float w = W[kk * Hn + t];
        #pragma unroll
        for (int rr = 0; rr < 8; rr++)
            a[rr] = fmaf(s[rr][kk], w, a[rr]);
    }
    #pragma unroll
    for (int rr = 0; rr < 8; rr++) {
        float p = fminf(fmaxf(a[rr], -40.f), 40.f) * TWO_LOG2E;
        float e;
        asm("ex2.approx.f32 %0, %1;" : "=f"(e) : "f"(p));
        outp[rr * Hn + t] = e;
    }
}

// ---------------------------------------------------------------------------
// Kernel 2: one block per (b, i) query row. 256 threads (8 warps).
// Pass 1: warp-per-key scores. Per h: d=fma(Eq,Ek,1); r=rcp(d); s=fma(-2w,r,s).
//         (tanh(x) = 1 - 2/(e^{2x}+1); Sum_h w_h hoisted into the init.)
// Pass 2: block softmax, exactly matching the -1e6 masking semantics;
//         valid_len == 0 degenerates to uniform weights over all KV.
// Pass 3: thread-per-output-column weighted sum of values, ILP 8.
// ---------------------------------------------------------------------------
__global__ void attn_kernel(const float* __restrict__ values,
                            const int* __restrict__ valid_lens,
                            const float* __restrict__ wv,
                            float* __restrict__ out) {
    const int row  = blockIdx.x;       // b*Qn + i  (R1 mapping: co-locates batches)
    const int b    = row >> 8;
    const int tid  = threadIdx.x;
    const int lane = tid & 31;
    const int warp = tid >> 5;

    __shared__ float s_sc[KVn];
    __shared__ float s_rmax[8];
    __shared__ float s_rsum[8];

    const int L     = valid_lens[b];
    const bool uni  = (L <= 0);        // all slots masked -> uniform softmax
    const int effL  = uni ? KVn : L;

    float Z;
    if (!uni) {
        // ---- Pass 1: scores ----
        const float4 q4 = *reinterpret_cast<const float4*>(&g_Eq[row * Hn + lane * 4]);
        const float4 w4 = *reinterpret_cast<const float4*>(&wv[lane * 4]);
        const float  wsum = ((w4.x + w4.y) + (w4.z + w4.w));
        const float  w2x = -2.f * w4.x, w2y = -2.f * w4.y,
                     w2z = -2.f * w4.z, w2w = -2.f * w4.w;
        const float* kb = g_Ek + b * KVn * Hn;

        int j = warp;
        // 2 keys per iteration (independent chains, MLP=2)
        for (; j + 8 < effL; j += 16) {
            const float4 ka = *reinterpret_cast<const float4*>(&kb[j * Hn + lane * 4]);
            const float4 kc = *reinterpret_cast<const float4*>(&kb[(j + 8) * Hn + lane * 4]);

            float r0, r1, r2, r3, t0, t1, t2, t3;
            asm("rcp.approx.f32 %0, %1;" : "=f"(r0) : "f"(fmaf(q4.x, ka.x, 1.f)));
            asm("rcp.approx.f32 %0, %1;" : "=f"(r1) : "f"(fmaf(q4.y, ka.y, 1.f)));
            asm("rcp.approx.f32 %0, %1;" : "=f"(r2) : "f"(fmaf(q4.z, ka.z, 1.f)));
            asm("rcp.approx.f32 %0, %1;" : "=f"(r3) : "f"(fmaf(q4.w, ka.w, 1.f)));
            asm("rcp.approx.f32 %0, %1;" : "=f"(t0) : "f"(fmaf(q4.x, kc.x, 1.f)));
            asm("rcp.approx.f32 %0, %1;" : "=f"(t1) : "f"(fmaf(q4.y, kc.y, 1.f)));
            asm("rcp.approx.f32 %0, %1;" : "=f"(t2) : "f"(fmaf(q4.z, kc.z, 1.f)));
            asm("rcp.approx.f32 %0, %1;" : "=f"(t3) : "f"(fmaf(q4.w, kc.w, 1.f)));

            float s0 = fmaf(w2x, r0, wsum);
            float s1 = fmaf(w2x, t0, wsum);
            s0 = fmaf(w2y, r1, s0);  s1 = fmaf(w2y, t1, s1);
            s0 = fmaf(w2z, r2, s0);  s1 = fmaf(w2z, t2, s1);
            s0 = fmaf(w2w, r3, s0);  s1 = fmaf(w2w, t3, s1);

            #pragma unroll
            for (int o = 16; o > 0; o >>= 1) {
                s0 += __shfl_xor_sync(0xffffffffu, s0, o);
                s1 += __shfl_xor_sync(0xffffffffu, s1, o);
            }
            if (lane == 0) {
                s_sc[j]     = s0;
                s_sc[j + 8] = s1;
            }
        }
        // remainder (at most one key per warp)
        if (j < effL) {
            const float4 ka = *reinterpret_cast<const float4*>(&kb[j * Hn + lane * 4]);
            float r0, r1, r2, r3;
            asm("rcp.approx.f32 %0, %1;" : "=f"(r0) : "f"(fmaf(q4.x, ka.x, 1.f)));
            asm("rcp.approx.f32 %0, %1;" : "=f"(r1) : "f"(fmaf(q4.y, ka.y, 1.f)));
            asm("rcp.approx.f32 %0, %1;" : "=f"(r2) : "f"(fmaf(q4.z, ka.z, 1.f)));
            asm("rcp.approx.f32 %0, %1;" : "=f"(r3) : "f"(fmaf(q4.w, ka.w, 1.f)));
            float s0 = fmaf(w2x, r0, wsum);
            s0 = fmaf(w2y, r1, s0);
            s0 = fmaf(w2z, r2, s0);
            s0 = fmaf(w2w, r3, s0);
            #pragma unroll
            for (int o = 16; o > 0; o >>= 1)
                s0 += __shfl_xor_sync(0xffffffffu, s0, o);
            if (lane == 0) s_sc[j] = s0;
        }
        __syncthreads();

        // ---- Pass 2a: block max over [0, effL) ----
        float m = -3.0e38f;
        for (int jj = tid; jj < effL; jj += 256) m = fmaxf(m, s_sc[jj]);
        #pragma unroll
        for (int o = 16; o > 0; o >>= 1)
            m = fmaxf(m, __shfl_xor_sync(0xffffffffu, m, o));
        if (lane == 0) s_rmax[warp] = m;
        __syncthreads();
        float M = s_rmax[0];
        #pragma unroll
        for (int k = 1; k < 8; k++) M = fmaxf(M, s_rmax[k]);

        // ---- Pass 2b: exp + sum ----
        float z = 0.f;
        for (int jj = tid; jj < effL; jj += 256) {
            const float e = __expf(s_sc[jj] - M);
            s_sc[jj] = e;
            z += e;
        }
        #pragma unroll
        for (int o = 16; o > 0; o >>= 1)
            z += __shfl_xor_sync(0xffffffffu, z, o);
        if (lane == 0) s_rsum[warp] = z;
        __syncthreads();
        Z = s_rsum[0];
        #pragma unroll
        for (int k = 1; k < 8; k++) Z += s_rsum[k];
    } else {
        // valid_len == 0: reference gives softmax over all -1e6 -> uniform
        for (int jj = tid; jj < KVn; jj += 256) s_sc[jj] = 1.0f;
        __syncthreads();
        Z = (float)KVn;
    }

    // ---- Pass 3: AV. Thread tid owns output column tid. ILP 8. ----
    const int c = tid;
    const float* vb = values + (size_t)b * KVn * VSn + c;
    float a[8];
    #pragma unroll
    for (int u = 0; u < 8; u++) a[u] = 0.f;

    int j = 0;
    for (; j + 8 <= effL; j += 8) {
        #pragma unroll
        for (int u = 0; u < 8; u++)
            a[u] = fmaf(s_sc[j + u], vb[(j + u) * VSn], a[u]);
    }
    for (; j < effL; j++) a[0] = fmaf(s_sc[j], vb[j * VSn], a[0]);

    const float acc = ((a[0] + a[1]) + (a[2] + a[3])) +
                      ((a[4] + a[5]) + (a[6] + a[7]));
    out[row * VSn + c] = acc / Z;
}

// ---------------------------------------------------------------------------
extern "C" void kernel_launch(void* const* d_in, const int* in_sizes, int n_in,
                              void* d_out, int out_size) {
    const float* queries = (const float*)d_in[0];
    const float* keys    = (const float*)d_in[1];
    const float* values  = (const float*)d_in[2];
    const int*   valid   = (const int*)d_in[3];
    const float* Wq      = (const float*)d_in[4];
    const float* Wk      = (const float*)d_in[5];
    const float* wv      = (const float*)d_in[6];
    float* out           = (float*)d_out;

    proj_kernel<<<(Bn * Qn + Bn * KVn) / 8, 128>>>(queries, keys, Wq, Wk);
    attn_kernel<<<Bn * Qn, 256>>>(values, valid, wv, out);
}

// round 5
// speedup vs baseline: 1.5326x; 1.0321x over previous
#include <cuda_runtime.h>

// Problem dims (fixed by the reference)
#define Bn  4
#define Qn  256
#define KVn 1024
#define Hn  128
#define VSn 256

// Scratch: Eq = e^{2*clamp(q_proj)}, Ek = e^{2*clamp(k_proj)}
__device__ float g_Eq[Bn * Qn * Hn];    // [B*Q, H]
__device__ float g_Ek[Bn * KVn * Hn];   // [B*KV, H]

// 2*log2(e): e^{2x} = 2^{x * 2*log2(e)}
#define TWO_LOG2E 2.885390081777927f

// ---------------------------------------------------------------------------
// Kernel 1: project rows and emit E = exp2(clamp(proj, +-40) * 2*log2(e)).
// Each block handles 8 rows; thread t owns output column t.
// ---------------------------------------------------------------------------
__global__ void proj_kernel(const float* __restrict__ queries,
                            const float* __restrict__ keys,
                            const float* __restrict__ Wq,
                            const float* __restrict__ Wk) {
    const int r0 = blockIdx.x * 8;
    const float* in;
    const float* W;
    float* outp;
    if (r0 < Bn * Qn) {
        in   = queries + r0 * Hn;
        W    = Wq;
        outp = g_Eq + r0 * Hn;
    } else {
        const int rr = r0 - Bn * Qn;
        in   = keys + rr * Hn;
        W    = Wk;
        outp = g_Ek + rr * Hn;
    }
    __shared__ float s[8][Hn];
    const int t = threadIdx.x;
    #pragma unroll
    for (int rr = 0; rr < 8; rr++) s[rr][t] = in[rr * Hn + t];
    __syncthreads();

    float a[8];
    #pragma unroll
    for (int rr = 0; rr < 8; rr++) a[rr] = 0.f;

    #pragma unroll 4
    for (int kk = 0; kk < Hn; kk++) {
        const float w = W[kk * Hn + t];
        #pragma unroll
        for (int rr = 0; rr < 8; rr++)
            a[rr] = fmaf(s[rr][kk], w, a[rr]);
    }
    #pragma unroll
    for (int rr = 0; rr < 8; rr++) {
        float p = fminf(fmaxf(a[rr], -40.f), 40.f) * TWO_LOG2E;
        float e;
        asm("ex2.approx.f32 %0, %1;" : "=f"(e) : "f"(p));
        outp[rr * Hn + t] = e;
    }
}

// ---------------------------------------------------------------------------
// Kernel 2: one block per (b, i) query row. 256 threads (8 warps).
// Pass 1: warp-per-key scores. Per h: d=fma(Eq,Ek,1); r=rcp(d); s=fma(-2w,r,s).
//         (tanh(x) = 1 - 2/(e^{2x}+1); Sum_h w_h hoisted into the init.)
// Pass 2: block softmax, exactly matching the -1e6 masking semantics;
//         valid_len == 0 degenerates to uniform weights over all KV.
// Pass 3: thread-per-output-column weighted sum of values, ILP 8.
// ---------------------------------------------------------------------------
__global__ void attn_kernel(const float* __restrict__ values,
                            const int* __restrict__ valid_lens,
                            const float* __restrict__ wv,
                            float* __restrict__ out) {
    const int row  = blockIdx.x;       // b*Qn + i  (R1 mapping: co-locates batches)
    const int b    = row >> 8;
    const int tid  = threadIdx.x;
    const int lane = tid & 31;
    const int warp = tid >> 5;

    __shared__ float s_sc[KVn];
    __shared__ float s_rmax[8];
    __shared__ float s_rsum[8];

    const int L     = valid_lens[b];
    const bool uni  = (L <= 0);        // all slots masked -> uniform softmax
    const int effL  = uni ? KVn : L;

    float Z;
    if (!uni) {
        // ---- Pass 1: scores ----
        const float4 q4 = *reinterpret_cast<const float4*>(&g_Eq[row * Hn + lane * 4]);
        const float4 w4 = *reinterpret_cast<const float4*>(&wv[lane * 4]);
        const float  wsum = ((w4.x + w4.y) + (w4.z + w4.w));
        const float  w2x = -2.f * w4.x, w2y = -2.f * w4.y,
                     w2z = -2.f * w4.z, w2w = -2.f * w4.w;
        const float* kb = g_Ek + b * KVn * Hn;

        int j = warp;
        // 2 keys per iteration (independent chains, MLP=2)
        for (; j + 8 < effL; j += 16) {
            const float4 ka = *reinterpret_cast<const float4*>(&kb[j * Hn + lane * 4]);
            const float4 kc = *reinterpret_cast<const float4*>(&kb[(j + 8) * Hn + lane * 4]);

            float r0, r1, r2, r3, t0, t1, t2, t3;
            asm("rcp.approx.f32 %0, %1;" : "=f"(r0) : "f"(fmaf(q4.x, ka.x, 1.f)));
            asm("rcp.approx.f32 %0, %1;" : "=f"(r1) : "f"(fmaf(q4.y, ka.y, 1.f)));
            asm("rcp.approx.f32 %0, %1;" : "=f"(r2) : "f"(fmaf(q4.z, ka.z, 1.f)));
            asm("rcp.approx.f32 %0, %1;" : "=f"(r3) : "f"(fmaf(q4.w, ka.w, 1.f)));
            asm("rcp.approx.f32 %0, %1;" : "=f"(t0) : "f"(fmaf(q4.x, kc.x, 1.f)));
            asm("rcp.approx.f32 %0, %1;" : "=f"(t1) : "f"(fmaf(q4.y, kc.y, 1.f)));
            asm("rcp.approx.f32 %0, %1;" : "=f"(t2) : "f"(fmaf(q4.z, kc.z, 1.f)));
            asm("rcp.approx.f32 %0, %1;" : "=f"(t3) : "f"(fmaf(q4.w, kc.w, 1.f)));

            float s0 = fmaf(w2x, r0, wsum);
            float s1 = fmaf(w2x, t0, wsum);
            s0 = fmaf(w2y, r1, s0);  s1 = fmaf(w2y, t1, s1);
            s0 = fmaf(w2z, r2, s0);  s1 = fmaf(w2z, t2, s1);
            s0 = fmaf(w2w, r3, s0);  s1 = fmaf(w2w, t3, s1);

            #pragma unroll
            for (int o = 16; o > 0; o >>= 1) {
                s0 += __shfl_xor_sync(0xffffffffu, s0, o);
                s1 += __shfl_xor_sync(0xffffffffu, s1, o);
            }
            if (lane == 0) {
                s_sc[j]     = s0;
                s_sc[j + 8] = s1;
            }
        }
        // remainder (at most one key per warp)
        if (j < effL) {
            const float4 ka = *reinterpret_cast<const float4*>(&kb[j * Hn + lane * 4]);
            float r0, r1, r2, r3;
            asm("rcp.approx.f32 %0, %1;" : "=f"(r0) : "f"(fmaf(q4.x, ka.x, 1.f)));
            asm("rcp.approx.f32 %0, %1;" : "=f"(r1) : "f"(fmaf(q4.y, ka.y, 1.f)));
            asm("rcp.approx.f32 %0, %1;" : "=f"(r2) : "f"(fmaf(q4.z, ka.z, 1.f)));
            asm("rcp.approx.f32 %0, %1;" : "=f"(r3) : "f"(fmaf(q4.w, ka.w, 1.f)));
            float s0 = fmaf(w2x, r0, wsum);
            s0 = fmaf(w2y, r1, s0);
            s0 = fmaf(w2z, r2, s0);
            s0 = fmaf(w2w, r3, s0);
            #pragma unroll
            for (int o = 16; o > 0; o >>= 1)
                s0 += __shfl_xor_sync(0xffffffffu, s0, o);
            if (lane == 0) s_sc[j] = s0;
        }
        __syncthreads();

        // ---- Pass 2a: block max over [0, effL) ----
        float m = -3.0e38f;
        for (int jj = tid; jj < effL; jj += 256) m = fmaxf(m, s_sc[jj]);
        #pragma unroll
        for (int o = 16; o > 0; o >>= 1)
            m = fmaxf(m, __shfl_xor_sync(0xffffffffu, m, o));
        if (lane == 0) s_rmax[warp] = m;
        __syncthreads();
        float M = s_rmax[0];
        #pragma unroll
        for (int k = 1; k < 8; k++) M = fmaxf(M, s_rmax[k]);

        // ---- Pass 2b: exp + sum ----
        float z = 0.f;
        for (int jj = tid; jj < effL; jj += 256) {
            const float e = __expf(s_sc[jj] - M);
            s_sc[jj] = e;
            z += e;
        }
        #pragma unroll
        for (int o = 16; o > 0; o >>= 1)
            z += __shfl_xor_sync(0xffffffffu, z, o);
        if (lane == 0) s_rsum[warp] = z;
        __syncthreads();
        Z = s_rsum[0];
        #pragma unroll
        for (int k = 1; k < 8; k++) Z += s_rsum[k];
    } else {
        // valid_len == 0: reference gives softmax over all -1e6 -> uniform
        for (int jj = tid; jj < KVn; jj += 256) s_sc[jj] = 1.0f;
        __syncthreads();
        Z = (float)KVn;
    }

    // ---- Pass 3: AV. Thread tid owns output column tid. ILP 8. ----
    const int c = tid;
    const float* vb = values + (size_t)b * KVn * VSn + c;
    float a[8];
    #pragma unroll
    for (int u = 0; u < 8; u++) a[u] = 0.f;

    int j = 0;
    for (; j + 8 <= effL; j += 8) {
        #pragma unroll
        for (int u = 0; u < 8; u++)
            a[u] = fmaf(s_sc[j + u], vb[(j + u) * VSn], a[u]);
    }
    for (; j < effL; j++) a[0] = fmaf(s_sc[j], vb[j * VSn], a[0]);

    const float acc = ((a[0] + a[1]) + (a[2] + a[3])) +
                      ((a[4] + a[5]) + (a[6] + a[7]));
    out[row * VSn + c] = acc / Z;
}

// ---------------------------------------------------------------------------
extern "C" void kernel_launch(void* const* d_in, const int* in_sizes, int n_in,
                              void* d_out, int out_size) {
    const float* queries = (const float*)d_in[0];
    const float* keys    = (const float*)d_in[1];
    const float* values  = (const float*)d_in[2];
    const int*   valid   = (const int*)d_in[3];
    const float* Wq      = (const float*)d_in[4];
    const float* Wk      = (const float*)d_in[5];
    const float* wv      = (const float*)d_in[6];
    float* out           = (float*)d_out;

    proj_kernel<<<(Bn * Qn + Bn * KVn) / 8, 128>>>(queries, keys, Wq, Wk);
    attn_kernel<<<Bn * Qn, 256>>>(values, valid, wv, out);
}

// round 6
// speedup vs baseline: 1.6451x; 1.0734x over previous
#include <cuda_runtime.h>

// Problem dims (fixed by the reference)
#define Bn  4
#define Qn  256
#define KVn 1024
#define Hn  128
#define VSn 256

// Scratch: Eq = e^{2*clamp(q_proj)}, Ek = e^{2*clamp(k_proj)}
__device__ float g_Eq[Bn * Qn * Hn];    // [B*Q, H]
__device__ float g_Ek[Bn * KVn * Hn];   // [B*KV, H]

// 2*log2(e): e^{2x} = 2^{x * 2*log2(e)}
#define TWO_LOG2E 2.885390081777927f

// ---------------------------------------------------------------------------
// Kernel 1: project rows and emit E = exp2(clamp(proj, +-40) * 2*log2(e)).
// Each block handles 8 rows; thread t owns output column t.
// ---------------------------------------------------------------------------
__global__ void proj_kernel(const float* __restrict__ queries,
                            const float* __restrict__ keys,
                            const float* __restrict__ Wq,
                            const float* __restrict__ Wk) {
    const int r0 = blockIdx.x * 8;
    const float* in;
    const float* W;
    float* outp;
    if (r0 < Bn * Qn) {
        in   = queries + r0 * Hn;
        W    = Wq;
        outp = g_Eq + r0 * Hn;
    } else {
        const int rr = r0 - Bn * Qn;
        in   = keys + rr * Hn;
        W    = Wk;
        outp = g_Ek + rr * Hn;
    }
    __shared__ float s[8][Hn];
    const int t = threadIdx.x;
    #pragma unroll
    for (int rr = 0; rr < 8; rr++) s[rr][t] = in[rr * Hn + t];
    __syncthreads();

    float a[8];
    #pragma unroll
    for (int rr = 0; rr < 8; rr++) a[rr] = 0.f;

    #pragma unroll 4
    for (int kk = 0; kk < Hn; kk++) {
        const float w = W[kk * Hn + t];
        #pragma unroll
        for (int rr = 0; rr < 8; rr++)
            a[rr] = fmaf(s[rr][kk], w, a[rr]);
    }
    #pragma unroll
    for (int rr = 0; rr < 8; rr++) {
        float p = fminf(fmaxf(a[rr], -40.f), 40.f) * TWO_LOG2E;
        float e;
        asm("ex2.approx.f32 %0, %1;" : "=f"(e) : "f"(p));
        outp[rr * Hn + t] = e;
    }
}

// ---------------------------------------------------------------------------
// Kernel 2: one block per (b, i) query row. 256 threads (8 warps).
//
// Pass 1 (scores): 8-lane-per-key geometry. Within a warp:
//   sub = lane>>3 selects one of 4 keys, hb = (lane&7)*16 selects the
//   16-element h-chunk. Each lane does 16x {d=fma(Eq,Ek,1); r=rcp(d);
//   s=fma(-2w,r,s)} on two interleaved accumulator chains, then a 3-level
//   shfl_xor (1,2,4) reduces all 4 keys simultaneously.
//   tanh(x) = 1 - 2/(e^{2x}+1); Sum_h w_h hoisted into the accumulator init.
// Pass 2: block softmax, exactly matching the -1e6 masking semantics;
//         valid_len == 0 degenerates to uniform weights over all KV.
// Pass 3: thread-per-output-column weighted sum of values, ILP 8.
// ---------------------------------------------------------------------------
__global__ void attn_kernel(const float* __restrict__ values,
                            const int* __restrict__ valid_lens,
                            const float* __restrict__ wv,
                            float* __restrict__ out) {
    const int row  = blockIdx.x;       // b*Qn + i (co-locates same-batch blocks)
    const int b    = row >> 8;
    const int tid  = threadIdx.x;
    const int lane = tid & 31;
    const int warp = tid >> 5;

    __shared__ float s_sc[KVn];
    __shared__ float s_rmax[8];
    __shared__ float s_rsum[8];

    const int L     = valid_lens[b];
    const bool uni  = (L <= 0);        // all slots masked -> uniform softmax
    const int effL  = uni ? KVn : L;

    float Z;
    if (!uni) {
        // ---- Pass 1: scores ----
        const int sub = lane >> 3;          // which key of the quad (0..3)
        const int hb  = (lane & 7) << 4;    // h-chunk base (16 floats)

        // This lane's 16-element slices of Eq and -2*wv, plus partial wsum.
        float4 q4[4], w2[4];
        float wsum_l = 0.f;
        #pragma unroll
        for (int i = 0; i < 4; i++) {
            q4[i] = *reinterpret_cast<const float4*>(&g_Eq[row * Hn + hb + i * 4]);
            float4 w = *reinterpret_cast<const float4*>(&wv[hb + i * 4]);
            wsum_l += ((w.x + w.y) + (w.z + w.w));
            w2[i] = make_float4(-2.f * w.x, -2.f * w.y, -2.f * w.z, -2.f * w.w);
        }
        const float* kb = g_Ek + b * KVn * Hn;

        for (int j0 = warp * 4; j0 < effL; j0 += 32) {
            const int key = j0 + sub;
            const int kc  = (key < effL) ? key : (effL - 1);  // clamp (safe load)

            float4 k4[4];
            #pragma unroll
            for (int i = 0; i < 4; i++)
                k4[i] = *reinterpret_cast<const float4*>(&kb[kc * Hn + hb + i * 4]);

            // 16 independent rcp chains, two interleaved accumulators
            float sa = wsum_l, sb = 0.f;
            #pragma unroll
            for (int i = 0; i < 4; i++) {
                float r0, r1, r2, r3;
                asm("rcp.approx.f32 %0, %1;" : "=f"(r0) : "f"(fmaf(q4[i].x, k4[i].x, 1.f)));
                asm("rcp.approx.f32 %0, %1;" : "=f"(r1) : "f"(fmaf(q4[i].y, k4[i].y, 1.f)));
                asm("rcp.approx.f32 %0, %1;" : "=f"(r2) : "f"(fmaf(q4[i].z, k4[i].z, 1.f)));
                asm("rcp.approx.f32 %0, %1;" : "=f"(r3) : "f"(fmaf(q4[i].w, k4[i].w, 1.f)));
                sa = fmaf(w2[i].x, r0, sa);
                sb = fmaf(w2[i].y, r1, sb);
                sa = fmaf(w2[i].z, r2, sa);
                sb = fmaf(w2[i].w, r3, sb);
            }
            float s = sa + sb;

            // reduce across the 8 lanes of each key group (lanes differ in low 3 bits)
            s += __shfl_xor_sync(0xffffffffu, s, 1);
            s += __shfl_xor_sync(0xffffffffu, s, 2);
            s += __shfl_xor_sync(0xffffffffu, s, 4);

            if ((lane & 7) == 0 && key < effL) s_sc[key] = s;
        }
        __syncthreads();

        // ---- Pass 2a: block max over [0, effL) ----
        float m = -3.0e38f;
        for (int jj = tid; jj < effL; jj += 256) m = fmaxf(m, s_sc[jj]);
        #pragma unroll
        for (int o = 16; o > 0; o >>= 1)
            m = fmaxf(m, __shfl_xor_sync(0xffffffffu, m, o));
        if (lane == 0) s_rmax[warp] = m;
        __syncthreads();
        float M = s_rmax[0];
        #pragma unroll
        for (int k = 1; k < 8; k++) M = fmaxf(M, s_rmax[k]);

        // ---- Pass 2b: exp + sum ----
        float z = 0.f;
        for (int jj = tid; jj < effL; jj += 256) {
            const float e = __expf(s_sc[jj] - M);
            s_sc[jj] = e;
            z += e;
        }
        #pragma unroll
        for (int o = 16; o > 0; o >>= 1)
            z += __shfl_xor_sync(0xffffffffu, z, o);
        if (lane == 0) s_rsum[warp] = z;
        __syncthreads();
        Z = s_rsum[0];
        #pragma unroll
        for (int k = 1; k < 8; k++) Z += s_rsum[k];
    } else {
        // valid_len == 0: reference gives softmax over all -1e6 -> uniform
        for (int jj = tid; jj < KVn; jj += 256) s_sc[jj] = 1.0f;
        __syncthreads();
        Z = (float)KVn;
    }

    // ---- Pass 3: AV. Thread tid owns output column tid. ILP 8. ----
    const int c = tid;
    const float* vb = values + (size_t)b * KVn * VSn + c;
    float a[8];
    #pragma unroll
    for (int u = 0; u < 8; u++) a[u] = 0.f;

    int j = 0;
    for (; j + 8 <= effL; j += 8) {
        #pragma unroll
        for (int u = 0; u < 8; u++)
            a[u] = fmaf(s_sc[j + u], vb[(j + u) * VSn], a[u]);
    }
    for (; j < effL; j++) a[0] = fmaf(s_sc[j], vb[j * VSn], a[0]);

    const float acc = ((a[0] + a[1]) + (a[2] + a[3])) +
                      ((a[4] + a[5]) + (a[6] + a[7]));
    out[row * VSn + c] = acc / Z;
}

// ---------------------------------------------------------------------------
extern "C" void kernel_launch(void* const* d_in, const int* in_sizes, int n_in,
                              void* d_out, int out_size) {
    const float* queries = (const float*)d_in[0];
    const float* keys    = (const float*)d_in[1];
    const float* values  = (const float*)d_in[2];
    const int*   valid   = (const int*)d_in[3];
    const float* Wq      = (const float*)d_in[4];
    const float* Wk      = (const float*)d_in[5];
    const float* wv      = (const float*)d_in[6];
    float* out           = (float*)d_out;

    proj_kernel<<<(Bn * Qn + Bn * KVn) / 8, 128>>>(queries, keys, Wq, Wk);
    attn_kernel<<<Bn * Qn, 256>>>(values, valid, wv, out);
}